// round 2
// baseline (speedup 1.0000x reference)
#include <cuda_runtime.h>
#include <math.h>

#define D_DIM 1024
#define H_DIM 1024
#define E_DIM 64

// 256 MB scratch for the hidden activations (allowed: __device__ global).
__device__ float g_H[65536u * 1024u];

// ---------------------------------------------------------------------------
// Kernel 1: H = gelu(x @ W1^T + b1)
// Classic SGEMM tiling: BM=BN=128, BK=8, 8x8 per-thread tile, 256 threads.
// A and W1 are both K-contiguous (row-major, K last), so C = A * B^T with
// both tiles loaded along K and stored transposed into smem.
// ---------------------------------------------------------------------------
__global__ __launch_bounds__(256, 2) void gemm1_gelu_kernel(
    const float* __restrict__ A,    // [M, 1024]
    const float* __restrict__ W1,   // [1024, 1024]
    const float* __restrict__ b1,   // [1024]
    float* __restrict__ Hout,       // [M, 1024]
    int M)
{
    __shared__ float As[8][128];
    __shared__ float Bs[8][128];

    const int tid = threadIdx.x;
    const int tx = tid & 15;   // output col group (tx*8 .. tx*8+7)
    const int ty = tid >> 4;   // output row group (ty*8 .. ty*8+7)
    const int bm = blockIdx.y * 128;
    const int bn = blockIdx.x * 128;

    // load mapping: each thread loads one float4 per tile per matrix
    const int lr = tid >> 1;          // row in tile, 0..127
    const int lc = (tid & 1) * 4;     // k offset, 0 or 4

    const float* Aptr = A  + (size_t)(bm + lr) * D_DIM + lc;
    const float* Bptr = W1 + (size_t)(bn + lr) * D_DIM + lc;

    float acc[8][8];
#pragma unroll
    for (int i = 0; i < 8; i++)
#pragma unroll
        for (int j = 0; j < 8; j++) acc[i][j] = 0.0f;

    for (int k0 = 0; k0 < D_DIM; k0 += 8) {
        float4 a4 = *(const float4*)(Aptr + k0);
        float4 b4 = *(const float4*)(Bptr + k0);
        As[lc + 0][lr] = a4.x; As[lc + 1][lr] = a4.y;
        As[lc + 2][lr] = a4.z; As[lc + 3][lr] = a4.w;
        Bs[lc + 0][lr] = b4.x; Bs[lc + 1][lr] = b4.y;
        Bs[lc + 2][lr] = b4.z; Bs[lc + 3][lr] = b4.w;
        __syncthreads();

#pragma unroll
        for (int kk = 0; kk < 8; kk++) {
            float a[8], b[8];
            *(float4*)(a)     = *(const float4*)&As[kk][ty * 8];
            *(float4*)(a + 4) = *(const float4*)&As[kk][ty * 8 + 4];
            *(float4*)(b)     = *(const float4*)&Bs[kk][tx * 8];
            *(float4*)(b + 4) = *(const float4*)&Bs[kk][tx * 8 + 4];
#pragma unroll
            for (int i = 0; i < 8; i++)
#pragma unroll
                for (int j = 0; j < 8; j++)
                    acc[i][j] = fmaf(a[i], b[j], acc[i][j]);
        }
        __syncthreads();
    }

    // epilogue: bias + exact (erf) gelu, vectorized store
    float bias[8];
    *(float4*)(bias)     = *(const float4*)&b1[bn + tx * 8];
    *(float4*)(bias + 4) = *(const float4*)&b1[bn + tx * 8 + 4];

#pragma unroll
    for (int i = 0; i < 8; i++) {
        const int row = bm + ty * 8 + i;
        float o[8];
#pragma unroll
        for (int j = 0; j < 8; j++) {
            float v = acc[i][j] + bias[j];
            o[j] = 0.5f * v * (1.0f + erff(v * 0.7071067811865476f));
        }
        float* dst = Hout + (size_t)row * H_DIM + bn + tx * 8;
        *(float4*)(dst)     = make_float4(o[0], o[1], o[2], o[3]);
        *(float4*)(dst + 4) = make_float4(o[4], o[5], o[6], o[7]);
    }
}

// ---------------------------------------------------------------------------
// Kernel 2: logits = (H @ W2^T + b2) / temp; top-2 mask; softmax -> out
// BM=128 rows, E=64 experts, BK=16. 256 threads, 8x4 per-thread tile.
// ---------------------------------------------------------------------------
__global__ __launch_bounds__(256, 1) void gemm2_router_kernel(
    const float* __restrict__ Hin,     // [M, 1024]
    const float* __restrict__ W2,      // [64, 1024]
    const float* __restrict__ b2,      // [64]
    const float* __restrict__ log_temp,// [1]
    float* __restrict__ out,           // [M, 64]
    int M)
{
    __shared__ float Hs[16][128];
    __shared__ float Ws[16][64];
    __shared__ float Ls[128][65];      // +1 pad: conflict-free row scans
    __shared__ float p1s[128], p2s[128];
    __shared__ int   i1s[128], i2s[128];

    const int tid = threadIdx.x;
    const int bm = blockIdx.x * 128;
    const int tx = tid & 15;   // expert group: cols tx*4 .. tx*4+3
    const int ty = tid >> 4;   // rows ty*8 .. ty*8+7

    // H tile load: 128x16 = 512 float4, 2 per thread
    const int hr0 = tid >> 2;              // 0..63  (f = tid)
    const int hc0 = (tid & 3) * 4;
    const int hr1 = (tid + 256) >> 2;      // 64..127 (f = tid+256)
    const int hc1 = hc0;                   // same (tid+256)&3 == tid&3
    // W2 tile load: 64x16 = 256 float4, 1 per thread
    const int wr = tid >> 2;               // 0..63
    const int wc = (tid & 3) * 4;

    float acc[8][4];
#pragma unroll
    for (int i = 0; i < 8; i++)
#pragma unroll
        for (int j = 0; j < 4; j++) acc[i][j] = 0.0f;

    for (int k0 = 0; k0 < H_DIM; k0 += 16) {
        float4 h0 = *(const float4*)(Hin + (size_t)(bm + hr0) * H_DIM + k0 + hc0);
        float4 h1 = *(const float4*)(Hin + (size_t)(bm + hr1) * H_DIM + k0 + hc1);
        float4 w4 = *(const float4*)(W2  + (size_t)wr * H_DIM + k0 + wc);
        Hs[hc0 + 0][hr0] = h0.x; Hs[hc0 + 1][hr0] = h0.y;
        Hs[hc0 + 2][hr0] = h0.z; Hs[hc0 + 3][hr0] = h0.w;
        Hs[hc1 + 0][hr1] = h1.x; Hs[hc1 + 1][hr1] = h1.y;
        Hs[hc1 + 2][hr1] = h1.z; Hs[hc1 + 3][hr1] = h1.w;
        Ws[wc + 0][wr] = w4.x; Ws[wc + 1][wr] = w4.y;
        Ws[wc + 2][wr] = w4.z; Ws[wc + 3][wr] = w4.w;
        __syncthreads();

#pragma unroll
        for (int kk = 0; kk < 16; kk++) {
            float a[8], b[4];
            *(float4*)(a)     = *(const float4*)&Hs[kk][ty * 8];
            *(float4*)(a + 4) = *(const float4*)&Hs[kk][ty * 8 + 4];
            *(float4*)(b)     = *(const float4*)&Ws[kk][tx * 4];
#pragma unroll
            for (int i = 0; i < 8; i++)
#pragma unroll
                for (int j = 0; j < 4; j++)
                    acc[i][j] = fmaf(a[i], b[j], acc[i][j]);
        }
        __syncthreads();
    }

    // temperature
    float t = expf(*log_temp);
    t = fminf(fmaxf(t, 1e-3f), 100.0f);
    const float it = 1.0f / t;

    // scaled logits -> smem
#pragma unroll
    for (int i = 0; i < 8; i++) {
#pragma unroll
        for (int j = 0; j < 4; j++) {
            const int col = tx * 4 + j;
            Ls[ty * 8 + i][col] = (acc[i][j] + b2[col]) * it;
        }
    }
    __syncthreads();

    // top-2 per row (strict > keeps lowest index on ties, matching lax.top_k)
    if (tid < 128) {
        float m1 = -INFINITY, m2 = -INFINITY;
        int i1 = -1, i2 = -1;
#pragma unroll 8
        for (int e = 0; e < E_DIM; e++) {
            float v = Ls[tid][e];
            if (v > m1) { m2 = m1; i2 = i1; m1 = v; i1 = e; }
            else if (v > m2) { m2 = v; i2 = e; }
        }
        float ed = expf(m2 - m1);        // <= 1, no overflow
        float s = 1.0f / (1.0f + ed);
        p1s[tid] = s;
        p2s[tid] = ed * s;
        i1s[tid] = i1;
        i2s[tid] = i2;
    }
    __syncthreads();

    // coalesced zero-filled output
    for (int idx = tid; idx < 128 * E_DIM; idx += 256) {
        const int r = idx >> 6;
        const int e = idx & 63;
        float v = 0.0f;
        if (e == i1s[r]) v = p1s[r];
        else if (e == i2s[r]) v = p2s[r];
        out[(size_t)(bm + r) * E_DIM + e] = v;
    }
}

// ---------------------------------------------------------------------------
// Launcher
// ---------------------------------------------------------------------------
extern "C" void kernel_launch(void* const* d_in, const int* in_sizes, int n_in,
                              void* d_out, int out_size) {
    const float* x  = (const float*)d_in[0];
    const float* W1 = (const float*)d_in[1];
    const float* b1 = (const float*)d_in[2];
    const float* W2 = (const float*)d_in[3];
    const float* b2 = (const float*)d_in[4];
    const float* lt = (const float*)d_in[5];
    float* out = (float*)d_out;

    const int M = in_sizes[0] / D_DIM;   // 65536

    float* Hbuf;
    cudaGetSymbolAddress((void**)&Hbuf, g_H);

    dim3 grid1(H_DIM / 128, M / 128);
    gemm1_gelu_kernel<<<grid1, 256>>>(x, W1, b1, Hbuf, M);

    dim3 grid2(M / 128);
    gemm2_router_kernel<<<grid2, 256>>>(Hbuf, W2, b2, lt, out, M);
}

// round 4
// speedup vs baseline: 2.8315x; 2.8315x over previous
#include <cuda_runtime.h>
#include <math.h>
#include <stdint.h>

#define D_DIM 1024
#define H_DIM 1024
#define E_DIM 64
#define M_TOTAL 65536

// tcgen05 is arch-SPECIFIC: only available when compiling the sm_103a (or
// family) target. The harness also runs a generic compute_103 pass, which
// must compile cleanly -> guard all tcgen05 PTX and provide an FFMA fallback.
#if defined(__CUDA_ARCH__) && (__CUDA_ARCH__ >= 1000) && \
    (defined(__CUDA_ARCH_FEAT_SM103_ALL) || defined(__CUDA_ARCH_FEAT_SM100_ALL) || \
     defined(__CUDA_ARCH_SPECIFIC__) || defined(__CUDA_ARCH_FAMILY_SPECIFIC__))
#define HAS_TCGEN05 1
#else
#define HAS_TCGEN05 0
#endif

// ---------------- static device scratch (no runtime alloc allowed) ----------
__device__ float g_H  [(size_t)M_TOTAL * H_DIM];   // 256 MB hidden
__device__ float g_xhi[(size_t)M_TOTAL * D_DIM];   // 256 MB
__device__ float g_xlo[(size_t)M_TOTAL * D_DIM];   // 256 MB
__device__ float g_w1hi[H_DIM * D_DIM];            // 4 MB
__device__ float g_w1lo[H_DIM * D_DIM];            // 4 MB

// ---------------- PTX helpers ----------------------------------------------
__device__ __forceinline__ uint32_t smem_u32(const void* p) {
    uint32_t a;
    asm("{ .reg .u64 t; cvta.to.shared.u64 t, %1; cvt.u32.u64 %0, t; }"
        : "=r"(a) : "l"(p));
    return a;
}

#define SWZ128(o) ((o) ^ (((o) >> 3) & 0x70))

__device__ __forceinline__ void mbar_init(uint32_t mbar, uint32_t cnt) {
    asm volatile("mbarrier.init.shared.b64 [%0], %1;" :: "r"(mbar), "r"(cnt) : "memory");
}
__device__ __forceinline__ void mbar_wait(uint32_t mbar, uint32_t parity) {
    asm volatile(
        "{\n\t"
        ".reg .pred P;\n\t"
        "WL%=:\n\t"
        "mbarrier.try_wait.parity.shared::cta.b64 P, [%0], %1, 0x989680;\n\t"
        "@P bra WD%=;\n\t"
        "bra WL%=;\n\t"
        "WD%=:\n\t"
        "}"
        :: "r"(mbar), "r"(parity) : "memory");
}
__device__ __forceinline__ void fence_proxy_async_cta() {
    asm volatile("fence.proxy.async.shared::cta;" ::: "memory");
}

#if HAS_TCGEN05
__device__ __forceinline__ uint64_t make_desc_sw128(uint32_t addr) {
    const uint64_t base = (2ull << 61) | (1ull << 46) | (64ull << 32) | (1ull << 16);
    return base | ((uint64_t)(addr >> 4) & 0x3FFF);
}

__device__ __forceinline__ void mma_tf32_ss(uint32_t d_tmem, uint64_t a_desc,
                                            uint64_t b_desc, uint32_t idesc,
                                            uint32_t enable_d) {
    asm volatile(
        "{\n\t"
        ".reg .pred p;\n\t"
        "setp.ne.u32 p, %5, 0;\n\t"
        "tcgen05.mma.cta_group::1.kind::tf32 [%0], %1, %2, %3, {%4, %4, %4, %4}, p;\n\t"
        "}"
        :: "r"(d_tmem), "l"(a_desc), "l"(b_desc), "r"(idesc), "r"(0u), "r"(enable_d)
        : "memory");
}
__device__ __forceinline__ void tc_commit(uint32_t mbar) {
    asm volatile(
        "tcgen05.commit.cta_group::1.mbarrier::arrive::one.shared::cluster.b64 [%0];"
        :: "r"(mbar) : "memory");
}
__device__ __forceinline__ void tc_alloc(uint32_t slot, uint32_t ncols) {
    asm volatile("tcgen05.alloc.cta_group::1.sync.aligned.shared::cta.b32 [%0], %1;"
                 :: "r"(slot), "r"(ncols) : "memory");
}
__device__ __forceinline__ void tc_dealloc(uint32_t tmem, uint32_t ncols) {
    asm volatile("tcgen05.relinquish_alloc_permit.cta_group::1.sync.aligned;");
    asm volatile("tcgen05.dealloc.cta_group::1.sync.aligned.b32 %0, %1;" :: "r"(tmem), "r"(ncols));
}
__device__ __forceinline__ void tc_fence_after() {
    asm volatile("tcgen05.fence::after_thread_sync;" ::: "memory");
}
__device__ __forceinline__ void tc_wait_ld() {
    asm volatile("tcgen05.wait::ld.sync.aligned;" ::: "memory");
}

#define TC_LD_X32(r, a)                                                       \
    asm volatile(                                                             \
        "tcgen05.ld.sync.aligned.32x32b.x32.b32 "                             \
        "{%0, %1, %2, %3, %4, %5, %6, %7, "                                   \
        " %8, %9, %10, %11, %12, %13, %14, %15, "                             \
        " %16, %17, %18, %19, %20, %21, %22, %23, "                           \
        " %24, %25, %26, %27, %28, %29, %30, %31}, [%32];"                    \
        : "=r"((r)[0]),  "=r"((r)[1]),  "=r"((r)[2]),  "=r"((r)[3]),          \
          "=r"((r)[4]),  "=r"((r)[5]),  "=r"((r)[6]),  "=r"((r)[7]),          \
          "=r"((r)[8]),  "=r"((r)[9]),  "=r"((r)[10]), "=r"((r)[11]),         \
          "=r"((r)[12]), "=r"((r)[13]), "=r"((r)[14]), "=r"((r)[15]),         \
          "=r"((r)[16]), "=r"((r)[17]), "=r"((r)[18]), "=r"((r)[19]),         \
          "=r"((r)[20]), "=r"((r)[21]), "=r"((r)[22]), "=r"((r)[23]),         \
          "=r"((r)[24]), "=r"((r)[25]), "=r"((r)[26]), "=r"((r)[27]),         \
          "=r"((r)[28]), "=r"((r)[29]), "=r"((r)[30]), "=r"((r)[31])          \
        : "r"(a))
#endif  // HAS_TCGEN05

// ---------------- split f32 -> tf32 hi/lo -----------------------------------
__device__ __forceinline__ float tf32_rnd(float a) {
    uint32_t r;
    asm("cvt.rna.tf32.f32 %0, %1;" : "=r"(r) : "f"(a));
    return __uint_as_float(r);
}

__global__ void split_tf32_kernel(const float4* __restrict__ src,
                                  float4* __restrict__ hi,
                                  float4* __restrict__ lo, int n4) {
    int i = blockIdx.x * blockDim.x + threadIdx.x;
    if (i >= n4) return;
    float4 v = src[i];
    float4 h, l;
    h.x = tf32_rnd(v.x); l.x = tf32_rnd(v.x - h.x);
    h.y = tf32_rnd(v.y); l.y = tf32_rnd(v.y - h.y);
    h.z = tf32_rnd(v.z); l.z = tf32_rnd(v.z - h.z);
    h.w = tf32_rnd(v.w); l.w = tf32_rnd(v.w - h.w);
    hi[i] = h;
    lo[i] = l;
}

// ---------------- GEMM1: H = gelu(x @ W1^T + b1) ----------------------------
// tcgen05 path: 3xTF32, BM=128, BN=256, BK=32, 2-stage smem pipeline.
// fallback path: fp32 FFMA 8x8 tiling over two 128-col halves.
// grid (H/256, M/128) = (4, 512), 256 threads, dynamic smem GEMM1_SMEM.
#define BK 32
#define NIT (D_DIM / BK)
#define STAGE_BYTES 98304
#define OFF_ALO 16384
#define OFF_BHI 32768
#define OFF_BLO 65536
#define GEMM1_SMEM (1024 + 2 * STAGE_BYTES)

// idesc: dtype f32(1), atype/btype tf32(2), N=256, M=128
#define IDESC_G1 ((1u << 4) | (2u << 7) | (2u << 10) | ((256u / 8) << 17) | ((128u / 16) << 24))

extern "C" __global__ void __launch_bounds__(256, 1) gemm1_kernel(
    const float* __restrict__ x,   const float* __restrict__ W1,
    const float* __restrict__ xhi, const float* __restrict__ xlo,
    const float* __restrict__ whi, const float* __restrict__ wlo,
    const float* __restrict__ b1,  float* __restrict__ Hout)
{
    extern __shared__ __align__(1024) char smem[];
    const int tid = threadIdx.x;
    const int bm = blockIdx.y * 128;

#if HAS_TCGEN05
    (void)x; (void)W1;
    const uint32_t sbase = smem_u32(smem);
    const int bn = blockIdx.x * 256;

    const uint32_t mb_done0 = sbase + 64;
    const uint32_t mb_done1 = sbase + 72;

    if (tid == 0) { mbar_init(mb_done0, 1); mbar_init(mb_done1, 1); }
    if (tid < 32) tc_alloc(sbase, 256);

    // per-thread load geometry: rows of 32 floats (128 B) SW128-swizzled
    const int r0 = tid >> 3;        // 0..31
    const int c4 = tid & 7;         // float4 slot in row
    uint32_t offA[4], offB[8];
#pragma unroll
    for (int j = 0; j < 4; j++)
        offA[j] = SWZ128((uint32_t)(r0 + 32 * j) * 128 + c4 * 16);
#pragma unroll
    for (int j = 0; j < 8; j++)
        offB[j] = SWZ128((uint32_t)(r0 + 32 * j) * 128 + c4 * 16);

    const float* pAh = xhi + (size_t)(bm + r0) * D_DIM + c4 * 4;
    const float* pAl = xlo + (size_t)(bm + r0) * D_DIM + c4 * 4;
    const float* pBh = whi + (size_t)(bn + r0) * D_DIM + c4 * 4;
    const float* pBl = wlo + (size_t)(bn + r0) * D_DIM + c4 * 4;

    // prologue: tile 0 -> stage 0
    {
        char* st = smem + 1024;
#pragma unroll
        for (int j = 0; j < 4; j++) {
            *(float4*)(st + offA[j])           = *(const float4*)(pAh + (size_t)(32 * j) * D_DIM);
            *(float4*)(st + OFF_ALO + offA[j]) = *(const float4*)(pAl + (size_t)(32 * j) * D_DIM);
        }
#pragma unroll
        for (int j = 0; j < 8; j++) {
            *(float4*)(st + OFF_BHI + offB[j]) = *(const float4*)(pBh + (size_t)(32 * j) * D_DIM);
            *(float4*)(st + OFF_BLO + offB[j]) = *(const float4*)(pBl + (size_t)(32 * j) * D_DIM);
        }
        fence_proxy_async_cta();
    }
    __syncthreads();

    uint32_t tmem_base;
    asm volatile("ld.shared.b32 %0, [%1];" : "=r"(tmem_base) : "r"(sbase));

    uint32_t ph0 = 0, ph1 = 0;

    for (int i = 0; i < NIT; i++) {
        const int s = i & 1;
        if (i > 0) __syncthreads();   // stage-s STS visible before MMA issue

        if (tid == 0) {
            uint32_t sb = sbase + 1024 + s * STAGE_BYTES;
            uint64_t dAh = make_desc_sw128(sb);
            uint64_t dAl = make_desc_sw128(sb + OFF_ALO);
            uint64_t dBh = make_desc_sw128(sb + OFF_BHI);
            uint64_t dBl = make_desc_sw128(sb + OFF_BLO);
#pragma unroll
            for (int ks = 0; ks < 4; ks++) {   // K=8 tf32 per MMA, +32B per step
                mma_tf32_ss(tmem_base, dAh + 2 * ks, dBh + 2 * ks, IDESC_G1,
                            (i == 0 && ks == 0) ? 0u : 1u);
                mma_tf32_ss(tmem_base, dAh + 2 * ks, dBl + 2 * ks, IDESC_G1, 1u);
                mma_tf32_ss(tmem_base, dAl + 2 * ks, dBh + 2 * ks, IDESC_G1, 1u);
            }
            tc_commit(s ? mb_done1 : mb_done0);
        }

        if (i + 1 < NIT) {
            const int t = s ^ 1;
            if (i >= 1) {   // wait: MMAs of iter i-1 (stage t) finished
                if (t == 0) { mbar_wait(mb_done0, ph0); ph0 ^= 1; }
                else        { mbar_wait(mb_done1, ph1); ph1 ^= 1; }
            }
            const int k0 = (i + 1) * BK;
            char* st = smem + 1024 + t * STAGE_BYTES;
#pragma unroll
            for (int j = 0; j < 4; j++) {
                *(float4*)(st + offA[j])           = *(const float4*)(pAh + (size_t)(32 * j) * D_DIM + k0);
                *(float4*)(st + OFF_ALO + offA[j]) = *(const float4*)(pAl + (size_t)(32 * j) * D_DIM + k0);
            }
#pragma unroll
            for (int j = 0; j < 8; j++) {
                *(float4*)(st + OFF_BHI + offB[j]) = *(const float4*)(pBh + (size_t)(32 * j) * D_DIM + k0);
                *(float4*)(st + OFF_BLO + offB[j]) = *(const float4*)(pBl + (size_t)(32 * j) * D_DIM + k0);
            }
            fence_proxy_async_cta();
        }
    }

    mbar_wait(mb_done1, ph1);   // final commit (iter NIT-1 is stage 1)
    tc_fence_after();

    // epilogue: warp w -> rows (w&3)*32, col half (w>>2)*128
    {
        const int w = tid >> 5, lane = tid & 31;
        const int colbase = (w >> 2) * 128;
        const int row = bm + (w & 3) * 32 + lane;
        float* hrow = Hout + (size_t)row * H_DIM + bn + colbase;
        const float* brow = b1 + bn + colbase;
#pragma unroll
        for (int ch = 0; ch < 4; ch++) {
            uint32_t r[32];
            TC_LD_X32(r, tmem_base + colbase + ch * 32);
            tc_wait_ld();
#pragma unroll
            for (int q = 0; q < 8; q++) {
                float4 bias = *(const float4*)(brow + ch * 32 + q * 4);
                float v0 = __uint_as_float(r[q * 4 + 0]) + bias.x;
                float v1 = __uint_as_float(r[q * 4 + 1]) + bias.y;
                float v2 = __uint_as_float(r[q * 4 + 2]) + bias.z;
                float v3 = __uint_as_float(r[q * 4 + 3]) + bias.w;
                float4 o;
                o.x = 0.5f * v0 * (1.0f + erff(v0 * 0.7071067811865476f));
                o.y = 0.5f * v1 * (1.0f + erff(v1 * 0.7071067811865476f));
                o.z = 0.5f * v2 * (1.0f + erff(v2 * 0.7071067811865476f));
                o.w = 0.5f * v3 * (1.0f + erff(v3 * 0.7071067811865476f));
                *(float4*)(hrow + ch * 32 + q * 4) = o;
            }
        }
    }

    __syncthreads();
    if (tid < 32) tc_dealloc(tmem_base, 256);

#else  // ---------- FFMA fallback (generic sm_103 pass): proven round-2 path --
    (void)xhi; (void)xlo; (void)whi; (void)wlo;
    float* As = (float*)smem;              // [8][128]
    float* Bs = As + 8 * 128;              // [8][128]

    const int tx = tid & 15;
    const int ty = tid >> 4;
    const int lr = tid >> 1;
    const int lc = (tid & 1) * 4;

    for (int half = 0; half < 2; half++) {
        const int bn = blockIdx.x * 256 + half * 128;
        const float* Aptr = x  + (size_t)(bm + lr) * D_DIM + lc;
        const float* Bptr = W1 + (size_t)(bn + lr) * D_DIM + lc;

        float acc[8][8];
#pragma unroll
        for (int i = 0; i < 8; i++)
#pragma unroll
            for (int j = 0; j < 8; j++) acc[i][j] = 0.0f;

        for (int k0 = 0; k0 < D_DIM; k0 += 8) {
            __syncthreads();
            float4 a4 = *(const float4*)(Aptr + k0);
            float4 b4 = *(const float4*)(Bptr + k0);
            As[(lc + 0) * 128 + lr] = a4.x; As[(lc + 1) * 128 + lr] = a4.y;
            As[(lc + 2) * 128 + lr] = a4.z; As[(lc + 3) * 128 + lr] = a4.w;
            Bs[(lc + 0) * 128 + lr] = b4.x; Bs[(lc + 1) * 128 + lr] = b4.y;
            Bs[(lc + 2) * 128 + lr] = b4.z; Bs[(lc + 3) * 128 + lr] = b4.w;
            __syncthreads();

#pragma unroll
            for (int kk = 0; kk < 8; kk++) {
                float a[8], b[8];
                *(float4*)(a)     = *(const float4*)&As[kk * 128 + ty * 8];
                *(float4*)(a + 4) = *(const float4*)&As[kk * 128 + ty * 8 + 4];
                *(float4*)(b)     = *(const float4*)&Bs[kk * 128 + tx * 8];
                *(float4*)(b + 4) = *(const float4*)&Bs[kk * 128 + tx * 8 + 4];
#pragma unroll
                for (int i = 0; i < 8; i++)
#pragma unroll
                    for (int j = 0; j < 8; j++)
                        acc[i][j] = fmaf(a[i], b[j], acc[i][j]);
            }
        }

        float bias[8];
        *(float4*)(bias)     = *(const float4*)&b1[bn + tx * 8];
        *(float4*)(bias + 4) = *(const float4*)&b1[bn + tx * 8 + 4];
#pragma unroll
        for (int i = 0; i < 8; i++) {
            const int row = bm + ty * 8 + i;
            float o[8];
#pragma unroll
            for (int j = 0; j < 8; j++) {
                float v = acc[i][j] + bias[j];
                o[j] = 0.5f * v * (1.0f + erff(v * 0.7071067811865476f));
            }
            float* dst = Hout + (size_t)row * H_DIM + bn + tx * 8;
            *(float4*)(dst)     = make_float4(o[0], o[1], o[2], o[3]);
            *(float4*)(dst + 4) = make_float4(o[4], o[5], o[6], o[7]);
        }
        __syncthreads();
    }
#endif
}

// ---------------- GEMM2 + top-2 softmax (fp32) ------------------------------
__global__ __launch_bounds__(256, 1) void gemm2_router_kernel(
    const float* __restrict__ Hin, const float* __restrict__ W2,
    const float* __restrict__ b2, const float* __restrict__ log_temp,
    float* __restrict__ out, int M)
{
    __shared__ float Hs[16][128];
    __shared__ float Ws[16][64];
    __shared__ float Ls[128][65];
    __shared__ float p1s[128], p2s[128];
    __shared__ int   i1s[128], i2s[128];

    const int tid = threadIdx.x;
    const int bm = blockIdx.x * 128;
    const int tx = tid & 15;
    const int ty = tid >> 4;

    const int hr0 = tid >> 2;
    const int hc0 = (tid & 3) * 4;
    const int hr1 = (tid + 256) >> 2;
    const int wr = tid >> 2;
    const int wc = (tid & 3) * 4;

    float acc[8][4];
#pragma unroll
    for (int i = 0; i < 8; i++)
#pragma unroll
        for (int j = 0; j < 4; j++) acc[i][j] = 0.0f;

    for (int k0 = 0; k0 < H_DIM; k0 += 16) {
        float4 h0 = *(const float4*)(Hin + (size_t)(bm + hr0) * H_DIM + k0 + hc0);
        float4 h1 = *(const float4*)(Hin + (size_t)(bm + hr1) * H_DIM + k0 + hc0);
        float4 w4 = *(const float4*)(W2  + (size_t)wr * H_DIM + k0 + wc);
        Hs[hc0 + 0][hr0] = h0.x; Hs[hc0 + 1][hr0] = h0.y;
        Hs[hc0 + 2][hr0] = h0.z; Hs[hc0 + 3][hr0] = h0.w;
        Hs[hc0 + 0][hr1] = h1.x; Hs[hc0 + 1][hr1] = h1.y;
        Hs[hc0 + 2][hr1] = h1.z; Hs[hc0 + 3][hr1] = h1.w;
        Ws[wc + 0][wr] = w4.x; Ws[wc + 1][wr] = w4.y;
        Ws[wc + 2][wr] = w4.z; Ws[wc + 3][wr] = w4.w;
        __syncthreads();

#pragma unroll
        for (int kk = 0; kk < 16; kk++) {
            float a[8], b[4];
            *(float4*)(a)     = *(const float4*)&Hs[kk][ty * 8];
            *(float4*)(a + 4) = *(const float4*)&Hs[kk][ty * 8 + 4];
            *(float4*)(b)     = *(const float4*)&Ws[kk][tx * 4];
#pragma unroll
            for (int i = 0; i < 8; i++)
#pragma unroll
                for (int j = 0; j < 4; j++)
                    acc[i][j] = fmaf(a[i], b[j], acc[i][j]);
        }
        __syncthreads();
    }

    float t = expf(*log_temp);
    t = fminf(fmaxf(t, 1e-3f), 100.0f);
    const float it = 1.0f / t;

#pragma unroll
    for (int i = 0; i < 8; i++)
#pragma unroll
        for (int j = 0; j < 4; j++) {
            const int col = tx * 4 + j;
            Ls[ty * 8 + i][col] = (acc[i][j] + b2[col]) * it;
        }
    __syncthreads();

    if (tid < 128) {
        float m1 = -INFINITY, m2 = -INFINITY;
        int i1 = -1, i2 = -1;
#pragma unroll 8
        for (int e = 0; e < E_DIM; e++) {
            float v = Ls[tid][e];
            if (v > m1) { m2 = m1; i2 = i1; m1 = v; i1 = e; }
            else if (v > m2) { m2 = v; i2 = e; }
        }
        float ed = expf(m2 - m1);
        float s = 1.0f / (1.0f + ed);
        p1s[tid] = s;
        p2s[tid] = ed * s;
        i1s[tid] = i1;
        i2s[tid] = i2;
    }
    __syncthreads();

    for (int idx = tid; idx < 128 * E_DIM; idx += 256) {
        const int r = idx >> 6;
        const int e = idx & 63;
        float v = 0.0f;
        if (e == i1s[r]) v = p1s[r];
        else if (e == i2s[r]) v = p2s[r];
        out[(size_t)(bm + r) * E_DIM + e] = v;
    }
}

// ---------------- launcher ---------------------------------------------------
extern "C" void kernel_launch(void* const* d_in, const int* in_sizes, int n_in,
                              void* d_out, int out_size) {
    const float* x  = (const float*)d_in[0];
    const float* W1 = (const float*)d_in[1];
    const float* b1 = (const float*)d_in[2];
    const float* W2 = (const float*)d_in[3];
    const float* b2 = (const float*)d_in[4];
    const float* lt = (const float*)d_in[5];
    float* out = (float*)d_out;

    const int M = in_sizes[0] / D_DIM;   // 65536

    float *Hbuf, *xhi, *xlo, *whi, *wlo;
    cudaGetSymbolAddress((void**)&Hbuf, g_H);
    cudaGetSymbolAddress((void**)&xhi, g_xhi);
    cudaGetSymbolAddress((void**)&xlo, g_xlo);
    cudaGetSymbolAddress((void**)&whi, g_w1hi);
    cudaGetSymbolAddress((void**)&wlo, g_w1lo);

    static int smem_set = 0;
    if (!smem_set) {
        cudaFuncSetAttribute(gemm1_kernel,
                             cudaFuncAttributeMaxDynamicSharedMemorySize, GEMM1_SMEM);
        smem_set = 1;
    }

    // split x and W1 into tf32 hi/lo (cheap; unused by fallback path)
    {
        int n4x = M * D_DIM / 4;
        split_tf32_kernel<<<n4x / 256, 256>>>((const float4*)x, (float4*)xhi,
                                              (float4*)xlo, n4x);
        int n4w = H_DIM * D_DIM / 4;
        split_tf32_kernel<<<n4w / 256, 256>>>((const float4*)W1, (float4*)whi,
                                              (float4*)wlo, n4w);
    }

    dim3 grid1(H_DIM / 256, M / 128);
    gemm1_kernel<<<grid1, 256, GEMM1_SMEM>>>(x, W1, xhi, xlo, whi, wlo, b1, Hbuf);

    dim3 grid2(M / 128);
    gemm2_router_kernel<<<grid2, 256>>>(Hbuf, W2, b2, lt, out, M);
}

// round 5
// speedup vs baseline: 3.2875x; 1.1610x over previous
#include <cuda_runtime.h>
#include <math.h>
#include <stdint.h>

#define D_DIM 1024
#define H_DIM 1024
#define E_DIM 64
#define M_TOTAL 65536

// tcgen05 is arch-SPECIFIC: guard so the generic compute_103 pass compiles.
#if defined(__CUDA_ARCH__) && (__CUDA_ARCH__ >= 1000) && \
    (defined(__CUDA_ARCH_FEAT_SM103_ALL) || defined(__CUDA_ARCH_FEAT_SM100_ALL) || \
     defined(__CUDA_ARCH_SPECIFIC__) || defined(__CUDA_ARCH_FAMILY_SPECIFIC__))
#define HAS_TCGEN05 1
#else
#define HAS_TCGEN05 0
#endif

// ---------------- static device scratch -------------------------------------
__device__ float g_H[(size_t)M_TOTAL * H_DIM];   // 256 MB hidden activations

// ---------------- PTX helpers ------------------------------------------------
__device__ __forceinline__ uint32_t smem_u32(const void* p) {
    uint32_t a;
    asm("{ .reg .u64 t; cvta.to.shared.u64 t, %1; cvt.u32.u64 %0, t; }"
        : "=r"(a) : "l"(p));
    return a;
}

#define SWZ128(o) ((o) ^ (((o) >> 3) & 0x70))

__device__ __forceinline__ void mbar_init(uint32_t mbar, uint32_t cnt) {
    asm volatile("mbarrier.init.shared.b64 [%0], %1;" :: "r"(mbar), "r"(cnt) : "memory");
}
__device__ __forceinline__ void mbar_wait(uint32_t mbar, uint32_t parity) {
    asm volatile(
        "{\n\t"
        ".reg .pred P;\n\t"
        "WL%=:\n\t"
        "mbarrier.try_wait.parity.shared::cta.b64 P, [%0], %1, 0x989680;\n\t"
        "@P bra WD%=;\n\t"
        "bra WL%=;\n\t"
        "WD%=:\n\t"
        "}"
        :: "r"(mbar), "r"(parity) : "memory");
}
__device__ __forceinline__ void fence_proxy_async_cta() {
    asm volatile("fence.proxy.async.shared::cta;" ::: "memory");
}

__device__ __forceinline__ float tf32_rnd(float a) {
    uint32_t r;
    asm("cvt.rna.tf32.f32 %0, %1;" : "=r"(r) : "f"(a));
    return __uint_as_float(r);
}
__device__ __forceinline__ void split4(float4 v, float4& h, float4& l) {
    h.x = tf32_rnd(v.x); l.x = tf32_rnd(v.x - h.x);
    h.y = tf32_rnd(v.y); l.y = tf32_rnd(v.y - h.y);
    h.z = tf32_rnd(v.z); l.z = tf32_rnd(v.z - h.z);
    h.w = tf32_rnd(v.w); l.w = tf32_rnd(v.w - h.w);
}

#if HAS_TCGEN05
__device__ __forceinline__ uint64_t make_desc_sw128(uint32_t addr) {
    const uint64_t base = (2ull << 61) | (1ull << 46) | (64ull << 32) | (1ull << 16);
    return base | ((uint64_t)(addr >> 4) & 0x3FFF);
}
__device__ __forceinline__ void mma_tf32_ss(uint32_t d_tmem, uint64_t a_desc,
                                            uint64_t b_desc, uint32_t idesc,
                                            uint32_t enable_d) {
    asm volatile(
        "{\n\t"
        ".reg .pred p;\n\t"
        "setp.ne.u32 p, %5, 0;\n\t"
        "tcgen05.mma.cta_group::1.kind::tf32 [%0], %1, %2, %3, {%4, %4, %4, %4}, p;\n\t"
        "}"
        :: "r"(d_tmem), "l"(a_desc), "l"(b_desc), "r"(idesc), "r"(0u), "r"(enable_d)
        : "memory");
}
__device__ __forceinline__ void tc_commit(uint32_t mbar) {
    asm volatile(
        "tcgen05.commit.cta_group::1.mbarrier::arrive::one.shared::cluster.b64 [%0];"
        :: "r"(mbar) : "memory");
}
__device__ __forceinline__ void tc_alloc(uint32_t slot, uint32_t ncols) {
    asm volatile("tcgen05.alloc.cta_group::1.sync.aligned.shared::cta.b32 [%0], %1;"
                 :: "r"(slot), "r"(ncols) : "memory");
}
__device__ __forceinline__ void tc_dealloc(uint32_t tmem, uint32_t ncols) {
    asm volatile("tcgen05.relinquish_alloc_permit.cta_group::1.sync.aligned;");
    asm volatile("tcgen05.dealloc.cta_group::1.sync.aligned.b32 %0, %1;" :: "r"(tmem), "r"(ncols));
}
__device__ __forceinline__ void tc_fence_after() {
    asm volatile("tcgen05.fence::after_thread_sync;" ::: "memory");
}
__device__ __forceinline__ void tc_wait_ld() {
    asm volatile("tcgen05.wait::ld.sync.aligned;" ::: "memory");
}

#define TC_LD_X32(r, a)                                                       \
    asm volatile(                                                             \
        "tcgen05.ld.sync.aligned.32x32b.x32.b32 "                             \
        "{%0, %1, %2, %3, %4, %5, %6, %7, "                                   \
        " %8, %9, %10, %11, %12, %13, %14, %15, "                             \
        " %16, %17, %18, %19, %20, %21, %22, %23, "                           \
        " %24, %25, %26, %27, %28, %29, %30, %31}, [%32];"                    \
        : "=r"((r)[0]),  "=r"((r)[1]),  "=r"((r)[2]),  "=r"((r)[3]),          \
          "=r"((r)[4]),  "=r"((r)[5]),  "=r"((r)[6]),  "=r"((r)[7]),          \
          "=r"((r)[8]),  "=r"((r)[9]),  "=r"((r)[10]), "=r"((r)[11]),         \
          "=r"((r)[12]), "=r"((r)[13]), "=r"((r)[14]), "=r"((r)[15]),         \
          "=r"((r)[16]), "=r"((r)[17]), "=r"((r)[18]), "=r"((r)[19]),         \
          "=r"((r)[20]), "=r"((r)[21]), "=r"((r)[22]), "=r"((r)[23]),         \
          "=r"((r)[24]), "=r"((r)[25]), "=r"((r)[26]), "=r"((r)[27]),         \
          "=r"((r)[28]), "=r"((r)[29]), "=r"((r)[30]), "=r"((r)[31])          \
        : "r"(a))
#endif  // HAS_TCGEN05

// ============================================================================
// GEMM1: H = gelu(x @ W1^T + b1).  3xTF32 tcgen05, split fused into loader.
// BM=128, BN=256, BK=32. grid (4, 512), 256 threads.
// ============================================================================
#define BK 32
#define NIT (D_DIM / BK)
#define STAGE_BYTES 98304
#define OFF_ALO 16384
#define OFF_BHI 32768
#define OFF_BLO 65536
#define GEMM1_SMEM (1024 + 2 * STAGE_BYTES)

#define IDESC_G1 ((1u << 4) | (2u << 7) | (2u << 10) | ((256u / 8) << 17) | ((128u / 16) << 24))

extern "C" __global__ void __launch_bounds__(256, 1) gemm1_kernel(
    const float* __restrict__ x, const float* __restrict__ W1,
    const float* __restrict__ b1, float* __restrict__ Hout)
{
    extern __shared__ __align__(1024) char smem[];
    const int tid = threadIdx.x;
    const int bm = blockIdx.y * 128;

#if HAS_TCGEN05
    const uint32_t sbase = smem_u32(smem);
    const int bn = blockIdx.x * 256;

    const uint32_t mb_done0 = sbase + 64;
    const uint32_t mb_done1 = sbase + 72;

    if (tid == 0) { mbar_init(mb_done0, 1); mbar_init(mb_done1, 1); }
    if (tid < 32) tc_alloc(sbase, 256);

    const int r0 = tid >> 3;        // 0..31
    const int c4 = tid & 7;
    uint32_t offA[4], offB[8];
#pragma unroll
    for (int j = 0; j < 4; j++)
        offA[j] = SWZ128((uint32_t)(r0 + 32 * j) * 128 + c4 * 16);
#pragma unroll
    for (int j = 0; j < 8; j++)
        offB[j] = SWZ128((uint32_t)(r0 + 32 * j) * 128 + c4 * 16);

    const float* pA = x  + (size_t)(bm + r0) * D_DIM + c4 * 4;
    const float* pB = W1 + (size_t)(bn + r0) * D_DIM + c4 * 4;

    // prologue: tile 0 -> stage 0 (f32 load, register split)
    {
        char* st = smem + 1024;
#pragma unroll
        for (int j = 0; j < 4; j++) {
            float4 v = *(const float4*)(pA + (size_t)(32 * j) * D_DIM);
            float4 h, l; split4(v, h, l);
            *(float4*)(st + offA[j])           = h;
            *(float4*)(st + OFF_ALO + offA[j]) = l;
        }
#pragma unroll
        for (int j = 0; j < 8; j++) {
            float4 v = *(const float4*)(pB + (size_t)(32 * j) * D_DIM);
            float4 h, l; split4(v, h, l);
            *(float4*)(st + OFF_BHI + offB[j]) = h;
            *(float4*)(st + OFF_BLO + offB[j]) = l;
        }
        fence_proxy_async_cta();
    }
    __syncthreads();

    uint32_t tmem_base;
    asm volatile("ld.shared.b32 %0, [%1];" : "=r"(tmem_base) : "r"(sbase));

    uint32_t ph0 = 0, ph1 = 0;

    for (int i = 0; i < NIT; i++) {
        const int s = i & 1;
        if (i > 0) __syncthreads();

        if (tid == 0) {
            uint32_t sb = sbase + 1024 + s * STAGE_BYTES;
            uint64_t dAh = make_desc_sw128(sb);
            uint64_t dAl = make_desc_sw128(sb + OFF_ALO);
            uint64_t dBh = make_desc_sw128(sb + OFF_BHI);
            uint64_t dBl = make_desc_sw128(sb + OFF_BLO);
#pragma unroll
            for (int ks = 0; ks < 4; ks++) {
                mma_tf32_ss(tmem_base, dAh + 2 * ks, dBh + 2 * ks, IDESC_G1,
                            (i == 0 && ks == 0) ? 0u : 1u);
                mma_tf32_ss(tmem_base, dAh + 2 * ks, dBl + 2 * ks, IDESC_G1, 1u);
                mma_tf32_ss(tmem_base, dAl + 2 * ks, dBh + 2 * ks, IDESC_G1, 1u);
            }
            tc_commit(s ? mb_done1 : mb_done0);
        }

        if (i + 1 < NIT) {
            const int t = s ^ 1;
            if (i >= 1) {
                if (t == 0) { mbar_wait(mb_done0, ph0); ph0 ^= 1; }
                else        { mbar_wait(mb_done1, ph1); ph1 ^= 1; }
            }
            const int k0 = (i + 1) * BK;
            char* st = smem + 1024 + t * STAGE_BYTES;
#pragma unroll
            for (int j = 0; j < 4; j++) {
                float4 v = *(const float4*)(pA + (size_t)(32 * j) * D_DIM + k0);
                float4 h, l; split4(v, h, l);
                *(float4*)(st + offA[j])           = h;
                *(float4*)(st + OFF_ALO + offA[j]) = l;
            }
#pragma unroll
            for (int j = 0; j < 8; j++) {
                float4 v = *(const float4*)(pB + (size_t)(32 * j) * D_DIM + k0);
                float4 h, l; split4(v, h, l);
                *(float4*)(st + OFF_BHI + offB[j]) = h;
                *(float4*)(st + OFF_BLO + offB[j]) = l;
            }
            fence_proxy_async_cta();
        }
    }

    mbar_wait(mb_done1, ph1);
    tc_fence_after();

    // epilogue: warp w -> rows (w&3)*32, col half (w>>2)*128
    {
        const int w = tid >> 5, lane = tid & 31;
        const int colbase = (w >> 2) * 128;
        const int row = bm + (w & 3) * 32 + lane;
        float* hrow = Hout + (size_t)row * H_DIM + bn + colbase;
        const float* brow = b1 + bn + colbase;
#pragma unroll
        for (int ch = 0; ch < 4; ch++) {
            uint32_t r[32];
            TC_LD_X32(r, tmem_base + colbase + ch * 32);
            tc_wait_ld();
#pragma unroll
            for (int q = 0; q < 8; q++) {
                float4 bias = *(const float4*)(brow + ch * 32 + q * 4);
                float v0 = __uint_as_float(r[q * 4 + 0]) + bias.x;
                float v1 = __uint_as_float(r[q * 4 + 1]) + bias.y;
                float v2 = __uint_as_float(r[q * 4 + 2]) + bias.z;
                float v3 = __uint_as_float(r[q * 4 + 3]) + bias.w;
                float4 o;
                o.x = 0.5f * v0 * (1.0f + erff(v0 * 0.7071067811865476f));
                o.y = 0.5f * v1 * (1.0f + erff(v1 * 0.7071067811865476f));
                o.z = 0.5f * v2 * (1.0f + erff(v2 * 0.7071067811865476f));
                o.w = 0.5f * v3 * (1.0f + erff(v3 * 0.7071067811865476f));
                *(float4*)(hrow + ch * 32 + q * 4) = o;
            }
        }
    }

    __syncthreads();
    if (tid < 32) tc_dealloc(tmem_base, 256);

#else  // ---------- FFMA fallback (generic pass) ----------------------------
    float* As = (float*)smem;
    float* Bs = As + 8 * 128;

    const int tx = tid & 15;
    const int ty = tid >> 4;
    const int lr = tid >> 1;
    const int lc = (tid & 1) * 4;

    for (int half = 0; half < 2; half++) {
        const int bn = blockIdx.x * 256 + half * 128;
        const float* Aptr = x  + (size_t)(bm + lr) * D_DIM + lc;
        const float* Bptr = W1 + (size_t)(bn + lr) * D_DIM + lc;

        float acc[8][8];
#pragma unroll
        for (int i = 0; i < 8; i++)
#pragma unroll
            for (int j = 0; j < 8; j++) acc[i][j] = 0.0f;

        for (int k0 = 0; k0 < D_DIM; k0 += 8) {
            __syncthreads();
            float4 a4 = *(const float4*)(Aptr + k0);
            float4 b4 = *(const float4*)(Bptr + k0);
            As[(lc + 0) * 128 + lr] = a4.x; As[(lc + 1) * 128 + lr] = a4.y;
            As[(lc + 2) * 128 + lr] = a4.z; As[(lc + 3) * 128 + lr] = a4.w;
            Bs[(lc + 0) * 128 + lr] = b4.x; Bs[(lc + 1) * 128 + lr] = b4.y;
            Bs[(lc + 2) * 128 + lr] = b4.z; Bs[(lc + 3) * 128 + lr] = b4.w;
            __syncthreads();
#pragma unroll
            for (int kk = 0; kk < 8; kk++) {
                float a[8], b[8];
                *(float4*)(a)     = *(const float4*)&As[kk * 128 + ty * 8];
                *(float4*)(a + 4) = *(const float4*)&As[kk * 128 + ty * 8 + 4];
                *(float4*)(b)     = *(const float4*)&Bs[kk * 128 + tx * 8];
                *(float4*)(b + 4) = *(const float4*)&Bs[kk * 128 + tx * 8 + 4];
#pragma unroll
                for (int i = 0; i < 8; i++)
#pragma unroll
                    for (int j = 0; j < 8; j++)
                        acc[i][j] = fmaf(a[i], b[j], acc[i][j]);
            }
        }

        float bias[8];
        *(float4*)(bias)     = *(const float4*)&b1[bn + tx * 8];
        *(float4*)(bias + 4) = *(const float4*)&b1[bn + tx * 8 + 4];
#pragma unroll
        for (int i = 0; i < 8; i++) {
            const int row = bm + ty * 8 + i;
            float o[8];
#pragma unroll
            for (int j = 0; j < 8; j++) {
                float v = acc[i][j] + bias[j];
                o[j] = 0.5f * v * (1.0f + erff(v * 0.7071067811865476f));
            }
            float* dst = Hout + (size_t)row * H_DIM + bn + tx * 8;
            *(float4*)(dst)     = make_float4(o[0], o[1], o[2], o[3]);
            *(float4*)(dst + 4) = make_float4(o[4], o[5], o[6], o[7]);
        }
        __syncthreads();
    }
#endif
}

// ============================================================================
// GEMM2: logits = (H @ W2^T + b2)/temp; top-2 softmax.  3xTF32 tcgen05.
// BM=128, BN=64(=E), BK=32. grid (512), 256 threads.
// ============================================================================
#define NIT2 (H_DIM / 32)
#define STAGE2_BYTES 49152
#define OFF2_HLO 16384
#define OFF2_WHI 32768
#define OFF2_WLO 40960
#define GEMM2_SMEM (1024 + 2 * STAGE2_BYTES)

#define IDESC_G2 ((1u << 4) | (2u << 7) | (2u << 10) | ((64u / 8) << 17) | ((128u / 16) << 24))

extern "C" __global__ void __launch_bounds__(256) gemm2_kernel(
    const float* __restrict__ Hin, const float* __restrict__ W2,
    const float* __restrict__ b2, const float* __restrict__ log_temp,
    float* __restrict__ out)
{
    extern __shared__ __align__(1024) char smem[];
    const int tid = threadIdx.x;
    const int bm = blockIdx.x * 128;

#if HAS_TCGEN05
    const uint32_t sbase = smem_u32(smem);
    const uint32_t mb_done0 = sbase + 64;
    const uint32_t mb_done1 = sbase + 72;

    if (tid == 0) { mbar_init(mb_done0, 1); mbar_init(mb_done1, 1); }
    if (tid < 32) tc_alloc(sbase, 64);

    const int r0 = tid >> 3;        // 0..31
    const int c4 = tid & 7;
    uint32_t offH[4], offW[2];
#pragma unroll
    for (int j = 0; j < 4; j++)
        offH[j] = SWZ128((uint32_t)(r0 + 32 * j) * 128 + c4 * 16);
#pragma unroll
    for (int j = 0; j < 2; j++)
        offW[j] = SWZ128((uint32_t)(r0 + 32 * j) * 128 + c4 * 16);

    const float* pH = Hin + (size_t)(bm + r0) * H_DIM + c4 * 4;
    const float* pW = W2  + (size_t)r0 * H_DIM + c4 * 4;

    {
        char* st = smem + 1024;
#pragma unroll
        for (int j = 0; j < 4; j++) {
            float4 v = *(const float4*)(pH + (size_t)(32 * j) * H_DIM);
            float4 h, l; split4(v, h, l);
            *(float4*)(st + offH[j])            = h;
            *(float4*)(st + OFF2_HLO + offH[j]) = l;
        }
#pragma unroll
        for (int j = 0; j < 2; j++) {
            float4 v = *(const float4*)(pW + (size_t)(32 * j) * H_DIM);
            float4 h, l; split4(v, h, l);
            *(float4*)(st + OFF2_WHI + offW[j]) = h;
            *(float4*)(st + OFF2_WLO + offW[j]) = l;
        }
        fence_proxy_async_cta();
    }
    __syncthreads();

    uint32_t tmem_base;
    asm volatile("ld.shared.b32 %0, [%1];" : "=r"(tmem_base) : "r"(sbase));

    uint32_t ph0 = 0, ph1 = 0;

    for (int i = 0; i < NIT2; i++) {
        const int s = i & 1;
        if (i > 0) __syncthreads();

        if (tid == 0) {
            uint32_t sb = sbase + 1024 + s * STAGE2_BYTES;
            uint64_t dHh = make_desc_sw128(sb);
            uint64_t dHl = make_desc_sw128(sb + OFF2_HLO);
            uint64_t dWh = make_desc_sw128(sb + OFF2_WHI);
            uint64_t dWl = make_desc_sw128(sb + OFF2_WLO);
#pragma unroll
            for (int ks = 0; ks < 4; ks++) {
                mma_tf32_ss(tmem_base, dHh + 2 * ks, dWh + 2 * ks, IDESC_G2,
                            (i == 0 && ks == 0) ? 0u : 1u);
                mma_tf32_ss(tmem_base, dHh + 2 * ks, dWl + 2 * ks, IDESC_G2, 1u);
                mma_tf32_ss(tmem_base, dHl + 2 * ks, dWh + 2 * ks, IDESC_G2, 1u);
            }
            tc_commit(s ? mb_done1 : mb_done0);
        }

        if (i + 1 < NIT2) {
            const int t = s ^ 1;
            if (i >= 1) {
                if (t == 0) { mbar_wait(mb_done0, ph0); ph0 ^= 1; }
                else        { mbar_wait(mb_done1, ph1); ph1 ^= 1; }
            }
            const int k0 = (i + 1) * 32;
            char* st = smem + 1024 + t * STAGE2_BYTES;
#pragma unroll
            for (int j = 0; j < 4; j++) {
                float4 v = *(const float4*)(pH + (size_t)(32 * j) * H_DIM + k0);
                float4 h, l; split4(v, h, l);
                *(float4*)(st + offH[j])            = h;
                *(float4*)(st + OFF2_HLO + offH[j]) = l;
            }
#pragma unroll
            for (int j = 0; j < 2; j++) {
                float4 v = *(const float4*)(pW + (size_t)(32 * j) * H_DIM + k0);
                float4 h, l; split4(v, h, l);
                *(float4*)(st + OFF2_WHI + offW[j]) = h;
                *(float4*)(st + OFF2_WLO + offW[j]) = l;
            }
            fence_proxy_async_cta();
        }
    }

    mbar_wait(mb_done1, ph1);
    tc_fence_after();

    // epilogue: stage smem is free now; carve scratch from it
    float* Ls  = (float*)(smem + 1024);            // [128][65]
    float* p1s = (float*)(smem + 1024 + 33280);
    float* p2s = p1s + 128;
    int*   i1s = (int*)(p2s + 128);
    int*   i2s = i1s + 128;

    float t = expf(*log_temp);
    t = fminf(fmaxf(t, 1e-3f), 100.0f);
    const float it = 1.0f / t;

    {
        const int w = tid >> 5, lane = tid & 31;
        const int row = (w & 3) * 32 + lane;       // 0..127
        const int colbase = (w >> 2) * 32;         // 0 or 32
        uint32_t r[32];
        TC_LD_X32(r, tmem_base + colbase);
        tc_wait_ld();
#pragma unroll
        for (int c = 0; c < 32; c++)
            Ls[row * 65 + colbase + c] =
                (__uint_as_float(r[c]) + b2[colbase + c]) * it;
    }
    __syncthreads();

    if (tid < 128) {
        float m1 = -INFINITY, m2 = -INFINITY;
        int i1 = -1, i2 = -1;
#pragma unroll 8
        for (int e = 0; e < E_DIM; e++) {
            float v = Ls[tid * 65 + e];
            if (v > m1) { m2 = m1; i2 = i1; m1 = v; i1 = e; }
            else if (v > m2) { m2 = v; i2 = e; }
        }
        float ed = expf(m2 - m1);
        float s = 1.0f / (1.0f + ed);
        p1s[tid] = s;
        p2s[tid] = ed * s;
        i1s[tid] = i1;
        i2s[tid] = i2;
    }
    __syncthreads();

    for (int idx = tid; idx < 128 * E_DIM; idx += 256) {
        const int r = idx >> 6;
        const int e = idx & 63;
        float v = 0.0f;
        if (e == i1s[r]) v = p1s[r];
        else if (e == i2s[r]) v = p2s[r];
        out[(size_t)(bm + r) * E_DIM + e] = v;
    }

    __syncthreads();
    if (tid < 32) tc_dealloc(tmem_base, 64);

#else  // ---------- FFMA fallback (generic pass) ----------------------------
    float* Hs  = (float*)smem;                     // [16][128]
    float* Ws  = Hs + 16 * 128;                    // [16][64]
    float* Ls  = Ws + 16 * 64;                     // [128][65]
    float* p1s = Ls + 128 * 65;
    float* p2s = p1s + 128;
    int*   i1s = (int*)(p2s + 128);
    int*   i2s = i1s + 128;

    const int tx = tid & 15;
    const int ty = tid >> 4;
    const int hr0 = tid >> 2;
    const int hc0 = (tid & 3) * 4;
    const int hr1 = (tid + 256) >> 2;
    const int wr = tid >> 2;
    const int wc = (tid & 3) * 4;

    float acc[8][4];
#pragma unroll
    for (int i = 0; i < 8; i++)
#pragma unroll
        for (int j = 0; j < 4; j++) acc[i][j] = 0.0f;

    for (int k0 = 0; k0 < H_DIM; k0 += 16) {
        __syncthreads();
        float4 h0 = *(const float4*)(Hin + (size_t)(bm + hr0) * H_DIM + k0 + hc0);
        float4 h1 = *(const float4*)(Hin + (size_t)(bm + hr1) * H_DIM + k0 + hc0);
        float4 w4 = *(const float4*)(W2  + (size_t)wr * H_DIM + k0 + wc);
        Hs[(hc0 + 0) * 128 + hr0] = h0.x; Hs[(hc0 + 1) * 128 + hr0] = h0.y;
        Hs[(hc0 + 2) * 128 + hr0] = h0.z; Hs[(hc0 + 3) * 128 + hr0] = h0.w;
        Hs[(hc0 + 0) * 128 + hr1] = h1.x; Hs[(hc0 + 1) * 128 + hr1] = h1.y;
        Hs[(hc0 + 2) * 128 + hr1] = h1.z; Hs[(hc0 + 3) * 128 + hr1] = h1.w;
        Ws[(wc + 0) * 64 + wr] = w4.x; Ws[(wc + 1) * 64 + wr] = w4.y;
        Ws[(wc + 2) * 64 + wr] = w4.z; Ws[(wc + 3) * 64 + wr] = w4.w;
        __syncthreads();
#pragma unroll
        for (int kk = 0; kk < 16; kk++) {
            float a[8], b[4];
            *(float4*)(a)     = *(const float4*)&Hs[kk * 128 + ty * 8];
            *(float4*)(a + 4) = *(const float4*)&Hs[kk * 128 + ty * 8 + 4];
            *(float4*)(b)     = *(const float4*)&Ws[kk * 64 + tx * 4];
#pragma unroll
            for (int i = 0; i < 8; i++)
#pragma unroll
                for (int j = 0; j < 4; j++)
                    acc[i][j] = fmaf(a[i], b[j], acc[i][j]);
        }
    }

    float t = expf(*log_temp);
    t = fminf(fmaxf(t, 1e-3f), 100.0f);
    const float it = 1.0f / t;

#pragma unroll
    for (int i = 0; i < 8; i++)
#pragma unroll
        for (int j = 0; j < 4; j++) {
            const int col = tx * 4 + j;
            Ls[(ty * 8 + i) * 65 + col] = (acc[i][j] + b2[col]) * it;
        }
    __syncthreads();

    if (tid < 128) {
        float m1 = -INFINITY, m2 = -INFINITY;
        int i1 = -1, i2 = -1;
#pragma unroll 8
        for (int e = 0; e < E_DIM; e++) {
            float v = Ls[tid * 65 + e];
            if (v > m1) { m2 = m1; i2 = i1; m1 = v; i1 = e; }
            else if (v > m2) { m2 = v; i2 = e; }
        }
        float ed = expf(m2 - m1);
        float s = 1.0f / (1.0f + ed);
        p1s[tid] = s;
        p2s[tid] = ed * s;
        i1s[tid] = i1;
        i2s[tid] = i2;
    }
    __syncthreads();

    for (int idx = tid; idx < 128 * E_DIM; idx += 256) {
        const int r = idx >> 6;
        const int e = idx & 63;
        float v = 0.0f;
        if (e == i1s[r]) v = p1s[r];
        else if (e == i2s[r]) v = p2s[r];
        out[(size_t)(bm + r) * E_DIM + e] = v;
    }
#endif
}

// ---------------- launcher ---------------------------------------------------
extern "C" void kernel_launch(void* const* d_in, const int* in_sizes, int n_in,
                              void* d_out, int out_size) {
    const float* x  = (const float*)d_in[0];
    const float* W1 = (const float*)d_in[1];
    const float* b1 = (const float*)d_in[2];
    const float* W2 = (const float*)d_in[3];
    const float* b2 = (const float*)d_in[4];
    const float* lt = (const float*)d_in[5];
    float* out = (float*)d_out;

    const int M = in_sizes[0] / D_DIM;   // 65536

    float* Hbuf;
    cudaGetSymbolAddress((void**)&Hbuf, g_H);

    static int smem_set = 0;
    if (!smem_set) {
        cudaFuncSetAttribute(gemm1_kernel,
                             cudaFuncAttributeMaxDynamicSharedMemorySize, GEMM1_SMEM);
        cudaFuncSetAttribute(gemm2_kernel,
                             cudaFuncAttributeMaxDynamicSharedMemorySize, GEMM2_SMEM);
        smem_set = 1;
    }

    dim3 grid1(H_DIM / 256, M / 128);
    gemm1_kernel<<<grid1, 256, GEMM1_SMEM>>>(x, W1, b1, Hbuf);

    dim3 grid2(M / 128);
    gemm2_kernel<<<grid2, 256, GEMM2_SMEM>>>(Hbuf, W2, b2, lt, out);
}

// round 6
// speedup vs baseline: 4.2357x; 1.2884x over previous
#include <cuda_runtime.h>
#include <math.h>
#include <stdint.h>

#define D_DIM 1024
#define H_DIM 1024
#define E_DIM 64
#define M_TOTAL 65536

#if defined(__CUDA_ARCH__) && (__CUDA_ARCH__ >= 1000) && \
    (defined(__CUDA_ARCH_FEAT_SM103_ALL) || defined(__CUDA_ARCH_FEAT_SM100_ALL) || \
     defined(__CUDA_ARCH_SPECIFIC__) || defined(__CUDA_ARCH_FAMILY_SPECIFIC__))
#define HAS_TCGEN05 1
#else
#define HAS_TCGEN05 0
#endif

__device__ float g_H[(size_t)M_TOTAL * H_DIM];   // 256 MB hidden activations

// ---------------- PTX helpers ------------------------------------------------
__device__ __forceinline__ uint32_t smem_u32(const void* p) {
    uint32_t a;
    asm("{ .reg .u64 t; cvta.to.shared.u64 t, %1; cvt.u32.u64 %0, t; }"
        : "=r"(a) : "l"(p));
    return a;
}

#define SWZ128(o) ((o) ^ (((o) >> 3) & 0x70))

__device__ __forceinline__ void mbar_init(uint32_t mbar, uint32_t cnt) {
    asm volatile("mbarrier.init.shared.b64 [%0], %1;" :: "r"(mbar), "r"(cnt) : "memory");
}
__device__ __forceinline__ void mbar_wait(uint32_t mbar, uint32_t parity) {
    asm volatile(
        "{\n\t"
        ".reg .pred P;\n\t"
        "WL%=:\n\t"
        "mbarrier.try_wait.parity.shared::cta.b64 P, [%0], %1, 0x989680;\n\t"
        "@P bra WD%=;\n\t"
        "bra WL%=;\n\t"
        "WD%=:\n\t"
        "}"
        :: "r"(mbar), "r"(parity) : "memory");
}
__device__ __forceinline__ void mbar_arrive(uint32_t mbar) {
    asm volatile("mbarrier.arrive.shared.b64 _, [%0];" :: "r"(mbar) : "memory");
}
__device__ __forceinline__ void fence_proxy_async_cta() {
    asm volatile("fence.proxy.async.shared::cta;" ::: "memory");
}

__device__ __forceinline__ float tf32_rnd(float a) {
    uint32_t r;
    asm("cvt.rna.tf32.f32 %0, %1;" : "=r"(r) : "f"(a));
    return __uint_as_float(r);
}
__device__ __forceinline__ void split4(float4 v, float4& h, float4& l) {
    h.x = tf32_rnd(v.x); l.x = tf32_rnd(v.x - h.x);
    h.y = tf32_rnd(v.y); l.y = tf32_rnd(v.y - h.y);
    h.z = tf32_rnd(v.z); l.z = tf32_rnd(v.z - h.z);
    h.w = tf32_rnd(v.w); l.w = tf32_rnd(v.w - h.w);
}

#if HAS_TCGEN05
__device__ __forceinline__ uint64_t make_desc_sw128(uint32_t addr) {
    const uint64_t base = (2ull << 61) | (1ull << 46) | (64ull << 32) | (1ull << 16);
    return base | ((uint64_t)(addr >> 4) & 0x3FFF);
}
__device__ __forceinline__ void mma_tf32_ss(uint32_t d_tmem, uint64_t a_desc,
                                            uint64_t b_desc, uint32_t idesc,
                                            uint32_t enable_d) {
    asm volatile(
        "{\n\t"
        ".reg .pred p;\n\t"
        "setp.ne.u32 p, %5, 0;\n\t"
        "tcgen05.mma.cta_group::1.kind::tf32 [%0], %1, %2, %3, {%4, %4, %4, %4}, p;\n\t"
        "}"
        :: "r"(d_tmem), "l"(a_desc), "l"(b_desc), "r"(idesc), "r"(0u), "r"(enable_d)
        : "memory");
}
__device__ __forceinline__ void tc_commit(uint32_t mbar) {
    asm volatile(
        "tcgen05.commit.cta_group::1.mbarrier::arrive::one.shared::cluster.b64 [%0];"
        :: "r"(mbar) : "memory");
}
__device__ __forceinline__ void tc_alloc(uint32_t slot, uint32_t ncols) {
    asm volatile("tcgen05.alloc.cta_group::1.sync.aligned.shared::cta.b32 [%0], %1;"
                 :: "r"(slot), "r"(ncols) : "memory");
}
__device__ __forceinline__ void tc_dealloc(uint32_t tmem, uint32_t ncols) {
    asm volatile("tcgen05.relinquish_alloc_permit.cta_group::1.sync.aligned;");
    asm volatile("tcgen05.dealloc.cta_group::1.sync.aligned.b32 %0, %1;" :: "r"(tmem), "r"(ncols));
}
__device__ __forceinline__ void tc_fence_after() {
    asm volatile("tcgen05.fence::after_thread_sync;" ::: "memory");
}
__device__ __forceinline__ void tc_wait_ld() {
    asm volatile("tcgen05.wait::ld.sync.aligned;" ::: "memory");
}

#define TC_LD_X32(r, a)                                                       \
    asm volatile(                                                             \
        "tcgen05.ld.sync.aligned.32x32b.x32.b32 "                             \
        "{%0, %1, %2, %3, %4, %5, %6, %7, "                                   \
        " %8, %9, %10, %11, %12, %13, %14, %15, "                             \
        " %16, %17, %18, %19, %20, %21, %22, %23, "                           \
        " %24, %25, %26, %27, %28, %29, %30, %31}, [%32];"                    \
        : "=r"((r)[0]),  "=r"((r)[1]),  "=r"((r)[2]),  "=r"((r)[3]),          \
          "=r"((r)[4]),  "=r"((r)[5]),  "=r"((r)[6]),  "=r"((r)[7]),          \
          "=r"((r)[8]),  "=r"((r)[9]),  "=r"((r)[10]), "=r"((r)[11]),         \
          "=r"((r)[12]), "=r"((r)[13]), "=r"((r)[14]), "=r"((r)[15]),         \
          "=r"((r)[16]), "=r"((r)[17]), "=r"((r)[18]), "=r"((r)[19]),         \
          "=r"((r)[20]), "=r"((r)[21]), "=r"((r)[22]), "=r"((r)[23]),         \
          "=r"((r)[24]), "=r"((r)[25]), "=r"((r)[26]), "=r"((r)[27]),         \
          "=r"((r)[28]), "=r"((r)[29]), "=r"((r)[30]), "=r"((r)[31])          \
        : "r"(a))
#endif  // HAS_TCGEN05

// ============================================================================
// GEMM1: H = gelu(x @ W1^T + b1).  3xTF32, producer/consumer mbarrier pipeline.
// BM=128, BN=256, BK=32, 2 stages. 288 threads (8 producer warps + MMA warp).
// ============================================================================
#define BK 32
#define NIT (D_DIM / BK)
#define STAGE_BYTES 98304
#define OFF_ALO 16384
#define OFF_BHI 32768
#define OFF_BLO 65536
#define GEMM1_SMEM (1024 + 2 * STAGE_BYTES)

#define IDESC_G1 ((1u << 4) | (2u << 7) | (2u << 10) | ((256u / 8) << 17) | ((128u / 16) << 24))

extern "C" __global__ void __launch_bounds__(288, 1) gemm1_kernel(
    const float* __restrict__ x, const float* __restrict__ W1,
    const float* __restrict__ b1, float* __restrict__ Hout)
{
    extern __shared__ __align__(1024) char smem[];
    const int tid = threadIdx.x;
    const int bm = blockIdx.y * 128;

#if HAS_TCGEN05
    const uint32_t sbase = smem_u32(smem);
    const int bn = blockIdx.x * 256;

    // mbar layout: full[s] = sbase+64+16s, empty[s] = +8
    if (tid == 0) {
#pragma unroll
        for (int s = 0; s < 2; s++) {
            mbar_init(sbase + 64 + 16 * s, 256);     // full: 256 producers
            mbar_init(sbase + 64 + 16 * s + 8, 1);   // empty: 1 commit
        }
    }
    if (tid >= 256) tc_alloc(sbase, 256);   // warp 8 (collective)
    __syncthreads();

    uint32_t tmem_base;
    asm volatile("ld.shared.b32 %0, [%1];" : "=r"(tmem_base) : "r"(sbase));

    if (tid < 256) {
        // ---------------- producers -----------------------------------------
        const int r0 = tid >> 3;
        const int c4 = tid & 7;
        uint32_t offA[4], offB[8];
#pragma unroll
        for (int j = 0; j < 4; j++)
            offA[j] = SWZ128((uint32_t)(r0 + 32 * j) * 128 + c4 * 16);
#pragma unroll
        for (int j = 0; j < 8; j++)
            offB[j] = SWZ128((uint32_t)(r0 + 32 * j) * 128 + c4 * 16);

        const float* pA = x  + (size_t)(bm + r0) * D_DIM + c4 * 4;
        const float* pB = W1 + (size_t)(bn + r0) * D_DIM + c4 * 4;

        uint32_t pe0 = 1, pe1 = 1;   // producer empty-parity (first wait passes)

        for (int ii = 0; ii < NIT / 2; ii++) {
#pragma unroll
            for (int s = 0; s < 2; s++) {
                const int i = ii * 2 + s;
                const uint32_t mb_full  = sbase + 64 + 16 * s;
                const uint32_t mb_empty = mb_full + 8;
                if (s == 0) { mbar_wait(mb_empty, pe0); pe0 ^= 1; }
                else        { mbar_wait(mb_empty, pe1); pe1 ^= 1; }

                const int k0 = i * BK;
                char* st = smem + 1024 + s * STAGE_BYTES;
#pragma unroll
                for (int j = 0; j < 4; j++) {
                    float4 v = *(const float4*)(pA + (size_t)(32 * j) * D_DIM + k0);
                    float4 h, l; split4(v, h, l);
                    *(float4*)(st + offA[j])           = h;
                    *(float4*)(st + OFF_ALO + offA[j]) = l;
                }
#pragma unroll
                for (int j = 0; j < 8; j++) {
                    float4 v = *(const float4*)(pB + (size_t)(32 * j) * D_DIM + k0);
                    float4 h, l; split4(v, h, l);
                    *(float4*)(st + OFF_BHI + offB[j]) = h;
                    *(float4*)(st + OFF_BLO + offB[j]) = l;
                }
                fence_proxy_async_cta();
                mbar_arrive(mb_full);
            }
        }

        // drain: last commits on both stages
        mbar_wait(sbase + 64 + 8, pe0);
        mbar_wait(sbase + 64 + 16 + 8, pe1);
        tc_fence_after();

        // ---------------- epilogue (8 warps, 256 cols) -----------------------
        const int w = tid >> 5, lane = tid & 31;
        const int colbase = (w >> 2) * 128;
        const int row = bm + (w & 3) * 32 + lane;
        float* hrow = Hout + (size_t)row * H_DIM + bn + colbase;
        const float* brow = b1 + bn + colbase;
#pragma unroll
        for (int ch = 0; ch < 4; ch++) {
            uint32_t r[32];
            TC_LD_X32(r, tmem_base + colbase + ch * 32);
            tc_wait_ld();
#pragma unroll
            for (int q = 0; q < 8; q++) {
                float4 bias = *(const float4*)(brow + ch * 32 + q * 4);
                float v0 = __uint_as_float(r[q * 4 + 0]) + bias.x;
                float v1 = __uint_as_float(r[q * 4 + 1]) + bias.y;
                float v2 = __uint_as_float(r[q * 4 + 2]) + bias.z;
                float v3 = __uint_as_float(r[q * 4 + 3]) + bias.w;
                float4 o;
                o.x = 0.5f * v0 * (1.0f + erff(v0 * 0.7071067811865476f));
                o.y = 0.5f * v1 * (1.0f + erff(v1 * 0.7071067811865476f));
                o.z = 0.5f * v2 * (1.0f + erff(v2 * 0.7071067811865476f));
                o.w = 0.5f * v3 * (1.0f + erff(v3 * 0.7071067811865476f));
                *(float4*)(hrow + ch * 32 + q * 4) = o;
            }
        }
    } else if (tid == 256) {
        // ---------------- MMA issuer ----------------------------------------
        uint32_t pf0 = 0, pf1 = 0;
        for (int ii = 0; ii < NIT / 2; ii++) {
#pragma unroll
            for (int s = 0; s < 2; s++) {
                const int i = ii * 2 + s;
                const uint32_t mb_full  = sbase + 64 + 16 * s;
                const uint32_t mb_empty = mb_full + 8;
                if (s == 0) { mbar_wait(mb_full, pf0); pf0 ^= 1; }
                else        { mbar_wait(mb_full, pf1); pf1 ^= 1; }

                uint32_t sb = sbase + 1024 + s * STAGE_BYTES;
                uint64_t dAh = make_desc_sw128(sb);
                uint64_t dAl = make_desc_sw128(sb + OFF_ALO);
                uint64_t dBh = make_desc_sw128(sb + OFF_BHI);
                uint64_t dBl = make_desc_sw128(sb + OFF_BLO);
#pragma unroll
                for (int ks = 0; ks < 4; ks++) {
                    mma_tf32_ss(tmem_base, dAh + 2 * ks, dBh + 2 * ks, IDESC_G1,
                                (i == 0 && ks == 0) ? 0u : 1u);
                    mma_tf32_ss(tmem_base, dAh + 2 * ks, dBl + 2 * ks, IDESC_G1, 1u);
                    mma_tf32_ss(tmem_base, dAl + 2 * ks, dBh + 2 * ks, IDESC_G1, 1u);
                }
                tc_commit(mb_empty);
            }
        }
    }

    __syncthreads();
    if (tid >= 256) tc_dealloc(tmem_base, 256);

#else  // ---------- FFMA fallback (generic pass; 288 threads, 256 active) ----
    float* As = (float*)smem;
    float* Bs = As + 8 * 128;

    const int tx = tid & 15;
    const int ty = tid >> 4;
    const int lr = tid >> 1;
    const int lc = (tid & 1) * 4;

    for (int half = 0; half < 2; half++) {
        const int bn = blockIdx.x * 256 + half * 128;
        float acc[8][8];
#pragma unroll
        for (int i = 0; i < 8; i++)
#pragma unroll
            for (int j = 0; j < 8; j++) acc[i][j] = 0.0f;

        for (int k0 = 0; k0 < D_DIM; k0 += 8) {
            __syncthreads();
            if (tid < 256) {
                float4 a4 = *(const float4*)(x  + (size_t)(bm + lr) * D_DIM + lc + k0);
                float4 b4 = *(const float4*)(W1 + (size_t)(bn + lr) * D_DIM + lc + k0);
                As[(lc + 0) * 128 + lr] = a4.x; As[(lc + 1) * 128 + lr] = a4.y;
                As[(lc + 2) * 128 + lr] = a4.z; As[(lc + 3) * 128 + lr] = a4.w;
                Bs[(lc + 0) * 128 + lr] = b4.x; Bs[(lc + 1) * 128 + lr] = b4.y;
                Bs[(lc + 2) * 128 + lr] = b4.z; Bs[(lc + 3) * 128 + lr] = b4.w;
            }
            __syncthreads();
            if (tid < 256) {
#pragma unroll
                for (int kk = 0; kk < 8; kk++) {
                    float a[8], b[8];
                    *(float4*)(a)     = *(const float4*)&As[kk * 128 + ty * 8];
                    *(float4*)(a + 4) = *(const float4*)&As[kk * 128 + ty * 8 + 4];
                    *(float4*)(b)     = *(const float4*)&Bs[kk * 128 + tx * 8];
                    *(float4*)(b + 4) = *(const float4*)&Bs[kk * 128 + tx * 8 + 4];
#pragma unroll
                    for (int i = 0; i < 8; i++)
#pragma unroll
                        for (int j = 0; j < 8; j++)
                            acc[i][j] = fmaf(a[i], b[j], acc[i][j]);
                }
            }
        }

        if (tid < 256) {
            float bias[8];
            *(float4*)(bias)     = *(const float4*)&b1[bn + tx * 8];
            *(float4*)(bias + 4) = *(const float4*)&b1[bn + tx * 8 + 4];
#pragma unroll
            for (int i = 0; i < 8; i++) {
                const int row = bm + ty * 8 + i;
                float o[8];
#pragma unroll
                for (int j = 0; j < 8; j++) {
                    float v = acc[i][j] + bias[j];
                    o[j] = 0.5f * v * (1.0f + erff(v * 0.7071067811865476f));
                }
                float* dst = Hout + (size_t)row * H_DIM + bn + tx * 8;
                *(float4*)(dst)     = make_float4(o[0], o[1], o[2], o[3]);
                *(float4*)(dst + 4) = make_float4(o[4], o[5], o[6], o[7]);
            }
        }
        __syncthreads();
    }
#endif
}

// ============================================================================
// GEMM2: logits = (H @ W2^T + b2)/temp; top-2 softmax.  3xTF32, 4-stage pipe.
// BM=128, BN=64, BK=32. 288 threads.
// ============================================================================
#define NIT2 (H_DIM / 32)
#define STAGE2_BYTES 49152
#define OFF2_HLO 16384
#define OFF2_WHI 32768
#define OFF2_WLO 40960
#define GEMM2_SMEM (1024 + 4 * STAGE2_BYTES)

#define IDESC_G2 ((1u << 4) | (2u << 7) | (2u << 10) | ((64u / 8) << 17) | ((128u / 16) << 24))

extern "C" __global__ void __launch_bounds__(288, 1) gemm2_kernel(
    const float* __restrict__ Hin, const float* __restrict__ W2,
    const float* __restrict__ b2, const float* __restrict__ log_temp,
    float* __restrict__ out)
{
    extern __shared__ __align__(1024) char smem[];
    const int tid = threadIdx.x;
    const int bm = blockIdx.x * 128;

#if HAS_TCGEN05
    const uint32_t sbase = smem_u32(smem);

    if (tid == 0) {
#pragma unroll
        for (int s = 0; s < 4; s++) {
            mbar_init(sbase + 64 + 16 * s, 256);
            mbar_init(sbase + 64 + 16 * s + 8, 1);
        }
    }
    if (tid >= 256) tc_alloc(sbase, 64);
    __syncthreads();

    uint32_t tmem_base;
    asm volatile("ld.shared.b32 %0, [%1];" : "=r"(tmem_base) : "r"(sbase));

    if (tid < 256) {
        const int r0 = tid >> 3;
        const int c4 = tid & 7;
        uint32_t offH[4], offW[2];
#pragma unroll
        for (int j = 0; j < 4; j++)
            offH[j] = SWZ128((uint32_t)(r0 + 32 * j) * 128 + c4 * 16);
#pragma unroll
        for (int j = 0; j < 2; j++)
            offW[j] = SWZ128((uint32_t)(r0 + 32 * j) * 128 + c4 * 16);

        const float* pH = Hin + (size_t)(bm + r0) * H_DIM + c4 * 4;
        const float* pW = W2  + (size_t)r0 * H_DIM + c4 * 4;

        uint32_t pe[4] = {1, 1, 1, 1};

        for (int ii = 0; ii < NIT2 / 4; ii++) {
#pragma unroll
            for (int s = 0; s < 4; s++) {
                const int i = ii * 4 + s;
                const uint32_t mb_full  = sbase + 64 + 16 * s;
                const uint32_t mb_empty = mb_full + 8;
                mbar_wait(mb_empty, pe[s]); pe[s] ^= 1;

                const int k0 = i * 32;
                char* st = smem + 1024 + s * STAGE2_BYTES;
#pragma unroll
                for (int j = 0; j < 4; j++) {
                    float4 v = *(const float4*)(pH + (size_t)(32 * j) * H_DIM + k0);
                    float4 h, l; split4(v, h, l);
                    *(float4*)(st + offH[j])            = h;
                    *(float4*)(st + OFF2_HLO + offH[j]) = l;
                }
#pragma unroll
                for (int j = 0; j < 2; j++) {
                    float4 v = *(const float4*)(pW + (size_t)(32 * j) * H_DIM + k0);
                    float4 h, l; split4(v, h, l);
                    *(float4*)(st + OFF2_WHI + offW[j]) = h;
                    *(float4*)(st + OFF2_WLO + offW[j]) = l;
                }
                fence_proxy_async_cta();
                mbar_arrive(mb_full);
            }
        }

#pragma unroll
        for (int s = 0; s < 4; s++)
            mbar_wait(sbase + 64 + 16 * s + 8, pe[s]);
        tc_fence_after();
    } else if (tid == 256) {
        uint32_t pf[4] = {0, 0, 0, 0};
        for (int ii = 0; ii < NIT2 / 4; ii++) {
#pragma unroll
            for (int s = 0; s < 4; s++) {
                const int i = ii * 4 + s;
                const uint32_t mb_full  = sbase + 64 + 16 * s;
                const uint32_t mb_empty = mb_full + 8;
                mbar_wait(mb_full, pf[s]); pf[s] ^= 1;

                uint32_t sb = sbase + 1024 + s * STAGE2_BYTES;
                uint64_t dHh = make_desc_sw128(sb);
                uint64_t dHl = make_desc_sw128(sb + OFF2_HLO);
                uint64_t dWh = make_desc_sw128(sb + OFF2_WHI);
                uint64_t dWl = make_desc_sw128(sb + OFF2_WLO);
#pragma unroll
                for (int ks = 0; ks < 4; ks++) {
                    mma_tf32_ss(tmem_base, dHh + 2 * ks, dWh + 2 * ks, IDESC_G2,
                                (i == 0 && ks == 0) ? 0u : 1u);
                    mma_tf32_ss(tmem_base, dHh + 2 * ks, dWl + 2 * ks, IDESC_G2, 1u);
                    mma_tf32_ss(tmem_base, dHl + 2 * ks, dWh + 2 * ks, IDESC_G2, 1u);
                }
                tc_commit(mb_empty);
            }
        }
    }
    __syncthreads();

    // ---------------- epilogue (stage smem reused as scratch) ----------------
    float* Ls  = (float*)(smem + 1024);            // [128][65]
    float* p1s = (float*)(smem + 1024 + 33280);
    float* p2s = p1s + 128;
    int*   i1s = (int*)(p2s + 128);
    int*   i2s = i1s + 128;

    float t = expf(*log_temp);
    t = fminf(fmaxf(t, 1e-3f), 100.0f);
    const float it = 1.0f / t;

    if (tid < 256) {
        const int w = tid >> 5, lane = tid & 31;
        const int row = (w & 3) * 32 + lane;
        const int colbase = (w >> 2) * 32;
        uint32_t r[32];
        TC_LD_X32(r, tmem_base + colbase);
        tc_wait_ld();
#pragma unroll
        for (int c = 0; c < 32; c++)
            Ls[row * 65 + colbase + c] =
                (__uint_as_float(r[c]) + b2[colbase + c]) * it;
    }
    __syncthreads();

    if (tid < 128) {
        float m1 = -INFINITY, m2 = -INFINITY;
        int i1 = -1, i2 = -1;
#pragma unroll 8
        for (int e = 0; e < E_DIM; e++) {
            float v = Ls[tid * 65 + e];
            if (v > m1) { m2 = m1; i2 = i1; m1 = v; i1 = e; }
            else if (v > m2) { m2 = v; i2 = e; }
        }
        float ed = expf(m2 - m1);
        float s = 1.0f / (1.0f + ed);
        p1s[tid] = s;
        p2s[tid] = ed * s;
        i1s[tid] = i1;
        i2s[tid] = i2;
    }
    __syncthreads();

    if (tid < 256) {
        for (int idx = tid; idx < 128 * E_DIM; idx += 256) {
            const int r = idx >> 6;
            const int e = idx & 63;
            float v = 0.0f;
            if (e == i1s[r]) v = p1s[r];
            else if (e == i2s[r]) v = p2s[r];
            out[(size_t)(bm + r) * E_DIM + e] = v;
        }
    }

    __syncthreads();
    if (tid >= 256) tc_dealloc(tmem_base, 64);

#else  // ---------- FFMA fallback (generic pass; 288 threads) ----------------
    float* Hs  = (float*)smem;
    float* Ws  = Hs + 16 * 128;
    float* Ls  = Ws + 16 * 64;
    float* p1s = Ls + 128 * 65;
    float* p2s = p1s + 128;
    int*   i1s = (int*)(p2s + 128);
    int*   i2s = i1s + 128;

    const int tx = tid & 15;
    const int ty = tid >> 4;
    const int hr0 = tid >> 2;
    const int hc0 = (tid & 3) * 4;
    const int hr1 = (tid + 256) >> 2;
    const int wr = tid >> 2;
    const int wc = (tid & 3) * 4;

    float acc[8][4];
#pragma unroll
    for (int i = 0; i < 8; i++)
#pragma unroll
        for (int j = 0; j < 4; j++) acc[i][j] = 0.0f;

    for (int k0 = 0; k0 < H_DIM; k0 += 16) {
        __syncthreads();
        if (tid < 256) {
            float4 h0 = *(const float4*)(Hin + (size_t)(bm + hr0) * H_DIM + k0 + hc0);
            float4 h1 = *(const float4*)(Hin + (size_t)(bm + hr1) * H_DIM + k0 + hc0);
            float4 w4 = *(const float4*)(W2  + (size_t)wr * H_DIM + k0 + wc);
            Hs[(hc0 + 0) * 128 + hr0] = h0.x; Hs[(hc0 + 1) * 128 + hr0] = h0.y;
            Hs[(hc0 + 2) * 128 + hr0] = h0.z; Hs[(hc0 + 3) * 128 + hr0] = h0.w;
            Hs[(hc0 + 0) * 128 + hr1] = h1.x; Hs[(hc0 + 1) * 128 + hr1] = h1.y;
            Hs[(hc0 + 2) * 128 + hr1] = h1.z; Hs[(hc0 + 3) * 128 + hr1] = h1.w;
            Ws[(wc + 0) * 64 + wr] = w4.x; Ws[(wc + 1) * 64 + wr] = w4.y;
            Ws[(wc + 2) * 64 + wr] = w4.z; Ws[(wc + 3) * 64 + wr] = w4.w;
        }
        __syncthreads();
        if (tid < 256) {
#pragma unroll
            for (int kk = 0; kk < 16; kk++) {
                float a[8], b[4];
                *(float4*)(a)     = *(const float4*)&Hs[kk * 128 + ty * 8];
                *(float4*)(a + 4) = *(const float4*)&Hs[kk * 128 + ty * 8 + 4];
                *(float4*)(b)     = *(const float4*)&Ws[kk * 64 + tx * 4];
#pragma unroll
                for (int i = 0; i < 8; i++)
#pragma unroll
                    for (int j = 0; j < 4; j++)
                        acc[i][j] = fmaf(a[i], b[j], acc[i][j]);
            }
        }
    }

    float t = expf(*log_temp);
    t = fminf(fmaxf(t, 1e-3f), 100.0f);
    const float it = 1.0f / t;

    if (tid < 256) {
#pragma unroll
        for (int i = 0; i < 8; i++)
#pragma unroll
            for (int j = 0; j < 4; j++) {
                const int col = tx * 4 + j;
                Ls[(ty * 8 + i) * 65 + col] = (acc[i][j] + b2[col]) * it;
            }
    }
    __syncthreads();

    if (tid < 128) {
        float m1 = -INFINITY, m2 = -INFINITY;
        int i1 = -1, i2 = -1;
#pragma unroll 8
        for (int e = 0; e < E_DIM; e++) {
            float v = Ls[tid * 65 + e];
            if (v > m1) { m2 = m1; i2 = i1; m1 = v; i1 = e; }
            else if (v > m2) { m2 = v; i2 = e; }
        }
        float ed = expf(m2 - m1);
        float s = 1.0f / (1.0f + ed);
        p1s[tid] = s;
        p2s[tid] = ed * s;
        i1s[tid] = i1;
        i2s[tid] = i2;
    }
    __syncthreads();

    if (tid < 256) {
        for (int idx = tid; idx < 128 * E_DIM; idx += 256) {
            const int r = idx >> 6;
            const int e = idx & 63;
            float v = 0.0f;
            if (e == i1s[r]) v = p1s[r];
            else if (e == i2s[r]) v = p2s[r];
            out[(size_t)(bm + r) * E_DIM + e] = v;
        }
    }
#endif
}

// ---------------- launcher ---------------------------------------------------
extern "C" void kernel_launch(void* const* d_in, const int* in_sizes, int n_in,
                              void* d_out, int out_size) {
    const float* x  = (const float*)d_in[0];
    const float* W1 = (const float*)d_in[1];
    const float* b1 = (const float*)d_in[2];
    const float* W2 = (const float*)d_in[3];
    const float* b2 = (const float*)d_in[4];
    const float* lt = (const float*)d_in[5];
    float* out = (float*)d_out;

    const int M = in_sizes[0] / D_DIM;   // 65536

    float* Hbuf;
    cudaGetSymbolAddress((void**)&Hbuf, g_H);

    static int smem_set = 0;
    if (!smem_set) {
        cudaFuncSetAttribute(gemm1_kernel,
                             cudaFuncAttributeMaxDynamicSharedMemorySize, GEMM1_SMEM);
        cudaFuncSetAttribute(gemm2_kernel,
                             cudaFuncAttributeMaxDynamicSharedMemorySize, GEMM2_SMEM);
        smem_set = 1;
    }

    dim3 grid1(H_DIM / 256, M / 128);
    gemm1_kernel<<<grid1, 288, GEMM1_SMEM>>>(x, W1, b1, Hbuf);

    dim3 grid2(M / 128);
    gemm2_kernel<<<grid2, 288, GEMM2_SMEM>>>(Hbuf, W2, b2, lt, out);
}